// round 6
// baseline (speedup 1.0000x reference)
#include <cuda_runtime.h>
#include <cuda_bf16.h>

// ODE-GRU: B=128, L=2048, I=D=64.
// Round 6: 2-GEMV critical path via precomputed M = w_hh@dw2, c = w_hh@db2:
//   gh = (h*w_hh^T + b_hh) + dt*(t1*M^T + c),  t1 = tanh(h*dw1^T + db1)
// gx = x*w_ih^T + b_ih hoisted out of the recurrence into a batch GEMM
// (201MB __device__ scratch). Recurrent kernel: 1 CTA/batch, 256 threads,
// 2 register-resident weight rows/thread, 3 barriers/step, all phases
// SMSP-balanced, all dots via fma.rn.f32x2.

#define NB 128
#define NL 2048
#define ND 64
#define NG 192
#define GXR 64   // (b,t)-rows per gx GEMM block

typedef unsigned long long u64;

__device__ float g_M[NG * ND];
__device__ float g_c[NG];
__device__ float g_gx[NB * NL * NG];   // 50,331,648 floats = 201 MB scratch

__device__ __forceinline__ u64 fma2(u64 a, u64 b, u64 c) {
    u64 d;
    asm("fma.rn.f32x2 %0, %1, %2, %3;" : "=l"(d) : "l"(a), "l"(b), "l"(c));
    return d;
}
__device__ __forceinline__ u64 add2(u64 a, u64 b) {
    u64 d;
    asm("add.rn.f32x2 %0, %1, %2;" : "=l"(d) : "l"(a), "l"(b));
    return d;
}
__device__ __forceinline__ u64 pk(float lo, float hi) {
    u64 r;
    asm("mov.b64 %0, {%1, %2};" : "=l"(r) : "f"(lo), "f"(hi));
    return r;
}

// dot(w_row[64], v[64]) + bias, w pre-packed f32x2.
__device__ __forceinline__ float dot64p(const u64* __restrict__ w,
                                        const float* __restrict__ v,
                                        float bias)
{
    const ulonglong2* __restrict__ v2 = (const ulonglong2*)v;
    u64 a0 = pk(bias, 0.f), a1 = 0ull, a2 = 0ull, a3 = 0ull;
#pragma unroll
    for (int q = 0; q < 8; q++) {
        ulonglong2 p = v2[2*q];
        ulonglong2 r = v2[2*q + 1];
        a0 = fma2(w[4*q+0], p.x, a0);
        a1 = fma2(w[4*q+1], p.y, a1);
        a2 = fma2(w[4*q+2], r.x, a2);
        a3 = fma2(w[4*q+3], r.y, a3);
    }
    u64 s = add2(add2(a0, a1), add2(a2, a3));
    float lo = __uint_as_float((unsigned)s);
    float hi = __uint_as_float((unsigned)(s >> 32));
    return lo + hi;
}

__device__ __forceinline__ float sigmoidf_(float a) {
    return __fdividef(1.f, 1.f + __expf(-a));
}
__device__ __forceinline__ float tanhf_fast(float x) {
    float e = __expf(2.f * x);
    return 1.f - __fdividef(2.f, e + 1.f);
}

// ---------------- setup: M = w_hh @ dw2  (192x64), c = w_hh @ db2 ----------
__global__ __launch_bounds__(64)
void setup_Mc_kernel(const float* __restrict__ w_hh,
                     const float* __restrict__ dw2,
                     const float* __restrict__ db2)
{
    const int k = blockIdx.x;    // 0..191
    const int j = threadIdx.x;   // 0..63
    __shared__ float row[ND];
    row[j] = w_hh[k * ND + j];
    __syncthreads();
    float acc = 0.f;
#pragma unroll 8
    for (int i = 0; i < ND; i++) acc = fmaf(row[i], dw2[i * ND + j], acc);
    g_M[k * ND + j] = acc;
    if (j == 0) {
        float c = 0.f;
        for (int i = 0; i < ND; i++) c = fmaf(row[i], db2[i], c);
        g_c[k] = c;
    }
}

// ---------------- gx = x @ w_ih^T + b_ih (masked: t>=sl -> b_ih) -----------
__global__ __launch_bounds__(192)
void gx_kernel(const float* __restrict__ x,
               const int*   __restrict__ seq,
               const float* __restrict__ w_ih,
               const float* __restrict__ b_ih)
{
    const int b     = blockIdx.x;
    const int chunk = blockIdx.y;
    const int k     = threadIdx.x;          // 0..191 output column
    __shared__ __align__(16) float xs[GXR * ND];

    u64 w[32];
    const u64* wp = (const u64*)(w_ih + k * ND);
#pragma unroll
    for (int q = 0; q < 32; q++) w[q] = wp[q];
    const float bias = b_ih[k];

    const int t0 = chunk * GXR;
    const float4* src = (const float4*)(x + ((size_t)b * NL + t0) * ND);
    float4* dst = (float4*)xs;
    for (int i = k; i < GXR * ND / 4; i += 192) dst[i] = src[i];
    const int sl = seq[b];
    __syncthreads();

    float* og = g_gx + ((size_t)b * NL + t0) * NG + k;
#pragma unroll 4
    for (int r = 0; r < GXR; r++) {
        const int t = t0 + r;
        float g = (t < sl) ? dot64p(w, xs + r * ND, bias) : bias;
        og[(size_t)r * NG] = g;
    }
}

// ---------------- recurrent kernel -----------------------------------------
__global__ __launch_bounds__(256, 1)
void odegru_kernel(const float* __restrict__ tdel,
                   const int*   __restrict__ seq,
                   const float* __restrict__ h0,
                   const float* __restrict__ b_hh,
                   const float* __restrict__ dw1,
                   const float* __restrict__ db1,
                   const float* __restrict__ dw2,
                   const float* __restrict__ db2,
                   const float* __restrict__ w_hh,
                   float* __restrict__ out)
{
    const int b    = blockIdx.x;
    const int tid  = threadIdx.x;
    const int lane = tid & 31;
    const int wid  = tid >> 5;

    __shared__ __align__(16) float sh_h[ND];
    __shared__ __align__(16) float sh_t1[ND];
    __shared__ __align__(16) float sh_G1[NG];  // h*w_hh^T + b_hh
    __shared__ __align__(16) float sh_G2[NG];  // t1*M^T
    __shared__ __align__(16) float sh_f[ND];   // t1*dw2^T + db2

    // ---- weight rows (2 per thread, packed f32x2) ----
    // Phase A rows: T0-63: dw1[j] (bias db1) -> t1
    //               T64-255: w_hh[tid-64] (bias b_hh) -> G1
    // Phase B rows: T0-191: M[tid] (bias 0) -> G2
    //               T192-255: dw2[tid-192] (bias db2) -> f
    u64 wA[32], wB[32];
    float bA, bB;
    const float* pA;
    const float* pB;
    if (tid < 64) {
        pA = dw1 + tid * ND;          bA = db1[tid];
        pB = g_M + tid * ND;          bB = 0.f;
    } else if (tid < 192) {
        pA = w_hh + (tid - 64) * ND;  bA = b_hh[tid - 64];
        pB = g_M + tid * ND;          bB = 0.f;
    } else {
        pA = w_hh + (tid - 64) * ND;  bA = b_hh[tid - 64];
        pB = dw2 + (tid - 192) * ND;  bB = db2[tid - 192];
    }
#pragma unroll
    for (int q = 0; q < 32; q++) {
        wA[q] = ((const u64*)pA)[q];
        wB[q] = ((const u64*)pB)[q];
    }

    const int sl = seq[b];
    float* outb = out + (size_t)b * NL * ND;

    // gate lanes: 8 per warp, j = wid*8 + lane  (balances phase C over SMSPs)
    const bool gate = (lane < 8);
    const int  j    = wid * 8 + lane;

    const float* gxb = g_gx + (size_t)b * NL * NG;
    const float* dtb = tdel + (size_t)b * NL;

    float c0 = 0.f, c1 = 0.f, c2 = 0.f;
    float cgx0 = 0.f, cgx1 = 0.f, cgx2 = 0.f, cdt = 0.f;
    if (gate) {
        c0 = g_c[j]; c1 = g_c[64 + j]; c2 = g_c[128 + j];
        cgx0 = gxb[j]; cgx1 = gxb[64 + j]; cgx2 = gxb[128 + j];
        cdt  = dtb[0];                       // sl >= 1 so t=0 is live
    }
    if (tid < 64) sh_h[tid] = h0[tid];

    float fin = 0.f;
    __syncthreads();

    for (int t = 0; t < NL; t++) {
        const int tn = t + 1;

        // prefetch step t+1 (consumed in next iteration's phase C)
        float nx0 = 0.f, nx1 = 0.f, nx2 = 0.f, ndt = 0.f;
        if (gate && tn < NL) {
            const float* g = gxb + (size_t)tn * NG;
            nx0 = g[j]; nx1 = g[64 + j]; nx2 = g[128 + j];
            ndt = dtb[tn];
        }

        // ---- Phase A: u = h*dw1^T+db1 (->t1) || G1 = h*w_hh^T + b_hh ----
        {
            float r = dot64p(wA, sh_h, bA);
            if (tid < 64) sh_t1[tid] = tanhf_fast(r);
            else          sh_G1[tid - 64] = r;
        }
        __syncthreads();

        // ---- Phase B: G2 = t1*M^T || f = t1*dw2^T + db2 ----
        {
            float r = dot64p(wB, sh_t1, bB);
            if (tid < 192) sh_G2[tid] = r;
            else           sh_f[tid - 192] = r;
        }
        __syncthreads();

        // ---- Phase C: gates (8 lanes per warp) ----
        if (gate) {
            const float dt = cdt;
            float ho = fmaf(dt, sh_f[j], sh_h[j]);
            float g0 = fmaf(dt, sh_G2[j]       + c0, sh_G1[j]);
            float g1 = fmaf(dt, sh_G2[64 + j]  + c1, sh_G1[64 + j]);
            float g2 = fmaf(dt, sh_G2[128 + j] + c2, sh_G1[128 + j]);
            float r  = sigmoidf_(cgx0 + g0);
            float z  = sigmoidf_(cgx1 + g1);
            float n  = tanhf_fast(fmaf(r, g2, cgx2));
            float hn = fmaf(z, ho - n, n);     // (1-z)*n + z*ho
            sh_h[j] = hn;
            outb[(size_t)t * ND + j] = hn;
            if (t == sl - 1) fin = hn;
            cgx0 = nx0; cgx1 = nx1; cgx2 = nx2;
            cdt  = (tn < sl) ? ndt : 0.f;      // PaddedBatch mask on dt
        }
        __syncthreads();
    }

    // final hidden state -> second output tensor (1, B, D)
    if (gate)
        out[(size_t)NB * NL * ND + (size_t)b * ND + j] = fin;
}

extern "C" void kernel_launch(void* const* d_in, const int* in_sizes, int n_in,
                              void* d_out, int out_size)
{
    const float* x    = (const float*)d_in[0];
    const float* tdel = (const float*)d_in[1];
    const int*   seq  = (const int*)  d_in[2];
    const float* h0   = (const float*)d_in[3];
    const float* w_ih = (const float*)d_in[4];
    const float* w_hh = (const float*)d_in[5];
    const float* b_ih = (const float*)d_in[6];
    const float* b_hh = (const float*)d_in[7];
    const float* dw1  = (const float*)d_in[8];
    const float* db1  = (const float*)d_in[9];
    const float* dw2  = (const float*)d_in[10];
    const float* db2  = (const float*)d_in[11];

    setup_Mc_kernel<<<NG, 64>>>(w_hh, dw2, db2);
    dim3 ggrid(NB, NL / GXR);
    gx_kernel<<<ggrid, 192>>>(x, seq, w_ih, b_ih);
    odegru_kernel<<<NB, 256>>>(tdel, seq, h0, b_hh, dw1, db1, dw2, db2, w_hh,
                               (float*)d_out);
}